// round 16
// baseline (speedup 1.0000x reference)
#include <cuda_runtime.h>
#include <cuda_bf16.h>

// Problem shape (fixed by the dataset): x:(B=16, D=1024), alphas/betas:(1, H=4)
#define D_DIM 1024
#define H_DIM 4
#define EPSILON 1e-8f
#define LOG2E 1.4426950408889634f
#define TINLINE 16             // max window accumulated inline
#define QCAP 1024              // deferred-item queue capacity (smem-limited)

__device__ __forceinline__ float frcp_approx(float d) {
    float r;
    asm("rcp.approx.f32 %0, %1;" : "=f"(r) : "f"(d));
    return r;
}
__device__ __forceinline__ float ex2_fast(float a) {
    float r;
    asm("ex2.approx.f32 %0, %1;" : "=f"(r) : "f"(a));
    return r;
}

// One block per batch row: sort + attention fused, no global scratch.
__global__ __launch_bounds__(D_DIM)
void fused_kernel(const float* __restrict__ x,
                  const float* __restrict__ aq, const float* __restrict__ bq,
                  const float* __restrict__ ak, const float* __restrict__ bk,
                  const float* __restrict__ av, const float* __restrict__ bv,
                  float* __restrict__ out)
{
    __shared__ float xs[D_DIM];            // sorted row (also sort staging)
    __shared__ int   qcount;
    __shared__ int   q_id[QCAP];           // (qi << 2) | h
    __shared__ int   q_lo[QCAP], q_hi[QCAP];
    __shared__ float q_qv[QCAP], q_cv[QCAP];
    __shared__ float satt_def[QCAP];

    const int b    = blockIdx.x;
    const int tid  = threadIdx.x;
    const int warp = tid >> 5;
    const int lane = tid & 31;

    // ---- Sort the row (bitonic; intra-warp stages via shfl, no barrier) ----
    const float xq = __ldg(x + b * D_DIM + tid);   // this thread's query value
    float v = xq;
#pragma unroll 1
    for (int k = 2; k <= D_DIM; k <<= 1) {
        const bool asc = ((tid & k) == 0);
#pragma unroll 1
        for (int j = k >> 1; j >= 32; j >>= 1) {
            xs[tid] = v;
            __syncthreads();
            float u = xs[tid ^ j];
            __syncthreads();
            bool keepmax = (((tid & j) != 0) == asc);
            v = keepmax ? fmaxf(v, u) : fminf(v, u);
        }
        int j0 = min(k >> 1, 16);
#pragma unroll 1
        for (int j = j0; j >= 1; j >>= 1) {
            float u = __shfl_xor_sync(0xffffffffu, v, j);
            bool keepmax = (((tid & j) != 0) == asc);
            v = keepmax ? fmaxf(v, u) : fminf(v, u);
        }
    }
    xs[tid] = v;
    if (tid == 0) qcount = 0;
    __syncthreads();

    // ---- Phase 1: 4 heads per thread (unrolled: 4 independent chains) ----
    float res = xq;                         // residual + accumulated heads
#pragma unroll
    for (int h = 0; h < H_DIM; h++) {
        const float q  = fmaf(aq[h], xq, bq[h]);
        const float a  = ak[h], bb = bk[h];

        // Insertion point of q among k_j = fma(a, xs[j], bb) (monotone, a>=0).
        int lo = 0, hi = D_DIM;
        while (lo < hi) {
            int mid = (lo + hi) >> 1;
            if (fmaf(a, xs[mid], bb) < q) lo = mid + 1; else hi = mid;
        }
        const int idx = lo;

        // Exact dmin from the two neighbors (reference formula).
        float dmin = 3.4e38f;
        if (idx < D_DIM) dmin = fabsf(fmaf(a, xs[idx], bb) - q);
        if (idx > 0)     dmin = fminf(dmin, fabsf(fmaf(a, xs[idx - 1], bb) - q));
        dmin += EPSILON;

        const float m    = frcp_approx(dmin);
        const float rthr = (m > 81.0f) ? frcp_approx(m - 80.0f) : 3.4e38f;
        const float c    = -m * LOG2E;

        // Window = k in [q - rthr, q + rthr]; upper_bound keeps k == q dups in.
        const float lob = q - rthr, hib = q + rthr;
        lo = 0; hi = D_DIM;
        while (lo < hi) {                   // first k >= lob
            int mid = (lo + hi) >> 1;
            if (fmaf(a, xs[mid], bb) < lob) lo = mid + 1; else hi = mid;
        }
        int wlo = lo;
        lo = 0; hi = D_DIM;
        while (lo < hi) {                   // first k > hib
            int mid = (lo + hi) >> 1;
            if (fmaf(a, xs[mid], bb) <= hib) lo = mid + 1; else hi = mid;
        }
        int whi = lo;
        wlo = min(wlo, max(idx - 1, 0));    // force argmin in => S0 > 0
        whi = max(whi, min(idx + 1, D_DIM));

        if (whi - wlo <= TINLINE) {
            float S0 = 0.f, S1 = 0.f;
            for (int j = wlo; j < whi; j++) {
                float xv = xs[j];
                float d  = fabsf(fmaf(a, xv, bb) - q) + EPSILON;
                float p  = ex2_fast(fmaf(frcp_approx(d), LOG2E, c));
                S0 += p;
                S1 = fmaf(p, xv, S1);
            }
            res += 0.5f * fmaf(av[h], S1 / S0, bv[h]);
        } else {
            int slot = atomicAdd(&qcount, 1);
            if (slot < QCAP) {
                q_id[slot] = (tid << 2) | h;
                q_lo[slot] = wlo;
                q_hi[slot] = whi;
                q_qv[slot] = q;
                q_cv[slot] = c;
            } else {
                // Overflow safety: serial accumulate (pathological only).
                float S0 = 0.f, S1 = 0.f;
                for (int j = wlo; j < whi; j++) {
                    float xv = xs[j];
                    float d  = fabsf(fmaf(a, xv, bb) - q) + EPSILON;
                    float p  = ex2_fast(fmaf(frcp_approx(d), LOG2E, c));
                    S0 += p;
                    S1 = fmaf(p, xv, S1);
                }
                res += 0.5f * fmaf(av[h], S1 / S0, bv[h]);
            }
        }
    }
    __syncthreads();

    // ---- Phase 2: one warp per deferred item (32 warps round-robin) ----
    const int nq = min(qcount, QCAP);
    for (int it = warp; it < nq; it += (D_DIM / 32)) {
        const int   h2  = q_id[it] & 3;
        const float qq  = q_qv[it], cc = q_cv[it];
        const float a2  = ak[h2],   b2 = bk[h2];
        const int   jlo = q_lo[it], jhi = q_hi[it];
        float S0 = 0.f, S1 = 0.f;
        for (int j = jlo + lane; j < jhi; j += 32) {
            float xv = xs[j];
            float d  = fabsf(fmaf(a2, xv, b2) - qq) + EPSILON;
            float p  = ex2_fast(fmaf(frcp_approx(d), LOG2E, cc));
            S0 += p;
            S1 = fmaf(p, xv, S1);
        }
#pragma unroll
        for (int o = 16; o; o >>= 1) {
            S0 += __shfl_xor_sync(0xffffffffu, S0, o);
            S1 += __shfl_xor_sync(0xffffffffu, S1, o);
        }
        if (lane == 0)
            satt_def[it] = 0.5f * fmaf(av[h2], S1 / S0, bv[h2]);
    }
    __syncthreads();

    // ---- Deterministic owner-scan combine of deferred results ----
    for (int it = 0; it < nq; it++)
        if ((q_id[it] >> 2) == tid) res += satt_def[it];

    out[b * D_DIM + tid] = res;
}

extern "C" void kernel_launch(void* const* d_in, const int* in_sizes, int n_in,
                              void* d_out, int out_size)
{
    const float* x  = (const float*)d_in[0];
    const float* aq = (const float*)d_in[1];
    const float* bq = (const float*)d_in[2];
    const float* ak = (const float*)d_in[3];
    const float* bk = (const float*)d_in[4];
    const float* av = (const float*)d_in[5];
    const float* bv = (const float*)d_in[6];
    float* out = (float*)d_out;

    const int B = in_sizes[0] / D_DIM;              // 16
    fused_kernel<<<B, D_DIM>>>(x, aq, bq, ak, bk, av, bv, out);
}

// round 17
// speedup vs baseline: 1.9969x; 1.9969x over previous
#include <cuda_runtime.h>
#include <cuda_bf16.h>

// Problem shape (fixed by the dataset): x:(B=16, D=1024), alphas/betas:(1, H=4)
#define D_DIM 1024
#define H_DIM 4
#define B_MAX 16
#define EPSILON 1e-8f
#define LOG2E 1.4426950408889634f
#define TB 128                 // attn kernel block size
#define QPB (TB / H_DIM)       // 32 queries per block
#define WSCAN 16               // half-width of the inline scan window

// Scratch for sorted batch rows (device global: no allocation in kernel_launch).
__device__ float g_sorted[B_MAX * D_DIM];

__device__ __forceinline__ float frcp_approx(float d) {
    float r;
    asm("rcp.approx.f32 %0, %1;" : "=f"(r) : "f"(d));
    return r;
}
__device__ __forceinline__ float ex2_fast(float a) {
    float r;
    asm("ex2.approx.f32 %0, %1;" : "=f"(r) : "f"(a));
    return r;
}

// ---- Kernel A: bitonic sort, 1024 threads, register value + shfl stages ----
__global__ __launch_bounds__(D_DIM)
void sort_kernel(const float* __restrict__ x)
{
    __shared__ float s[D_DIM];
    const int b   = blockIdx.x;
    const int tid = threadIdx.x;
    float v = __ldg(x + b * D_DIM + tid);
#pragma unroll 1
    for (int k = 2; k <= D_DIM; k <<= 1) {
        const bool asc = ((tid & k) == 0);
#pragma unroll 1
        for (int j = k >> 1; j >= 32; j >>= 1) {
            s[tid] = v;
            __syncthreads();
            float u = s[tid ^ j];
            __syncthreads();
            bool keepmax = (((tid & j) != 0) == asc);
            v = keepmax ? fmaxf(v, u) : fminf(v, u);
        }
        int j0 = min(k >> 1, 16);
#pragma unroll 1
        for (int j = j0; j >= 1; j >>= 1) {
            float u = __shfl_xor_sync(0xffffffffu, v, j);
            bool keepmax = (((tid & j) != 0) == asc);
            v = keepmax ? fmaxf(v, u) : fminf(v, u);
        }
    }
    g_sorted[b * D_DIM + tid] = v;
}

// ---- Kernel B: thread = (query, head). 1 search + +-16 scan; warp-ballot
// cooperative fallback for wide softmax windows. ----
__global__ __launch_bounds__(TB)
void attn_kernel(const float* __restrict__ x,
                 const float* __restrict__ aq, const float* __restrict__ bq,
                 const float* __restrict__ ak, const float* __restrict__ bk,
                 const float* __restrict__ av, const float* __restrict__ bv,
                 float* __restrict__ out)
{
    __shared__ float xs[D_DIM];            // sorted batch row
    __shared__ float satt[QPB][H_DIM];

    const int blocks_per_batch = D_DIM / QPB;   // 32
    const int b    = blockIdx.x / blocks_per_batch;
    const int i0   = (blockIdx.x % blocks_per_batch) * QPB;
    const int tid  = threadIdx.x;
    const int lane = tid & 31;

    // Stage sorted row (2 float4 per thread).
    ((float4*)xs)[tid]      = __ldg((const float4*)(g_sorted + b * D_DIM) + tid);
    ((float4*)xs)[tid + TB] = __ldg((const float4*)(g_sorted + b * D_DIM) + tid + TB);
    __syncthreads();

    const int   qloc = tid >> 2;
    const int   h    = tid & 3;
    const int   qi   = i0 + qloc;
    const float xq   = __ldg(x + b * D_DIM + qi);
    const float q    = fmaf(aq[h], xq, bq[h]);
    const float a    = ak[h], bb = bk[h];
    const float avh  = av[h], bvh = bv[h];

    // Search: insertion point of q among k_j = fma(a, xs[j], bb).
    // a >= 0 (alphas ~ U[0,1)) and RN-fma is monotone, so k is nondecreasing;
    // |k_j - q| is V-shaped with its min at idx-1 or idx.
    int lo = 0, hi = D_DIM;
#pragma unroll 1
    while (lo < hi) {
        int mid = (lo + hi) >> 1;
        if (fmaf(a, xs[mid], bb) < q) lo = mid + 1; else hi = mid;
    }
    const int idx = lo;

    // Exact dmin from the two neighbors (reference formula).
    float dmin = 3.4e38f;
    if (idx < D_DIM) dmin = fabsf(fmaf(a, xs[idx], bb) - q);
    if (idx > 0)     dmin = fminf(dmin, fabsf(fmaf(a, xs[idx - 1], bb) - q));
    dmin += EPSILON;

    // Shift point. Terms with s < m - 30 have weight < e^-30 ~ 9e-14 vs
    // S0 >= 1 -- negligible. 1.000002f guards rcp.approx rounding so the
    // argmin itself always tests live.
    const float m    = frcp_approx(dmin);
    const float rthr = (m > 31.0f) ? frcp_approx(m - 30.0f) * 1.000002f : 3.4e38f;
    const float c    = -m * LOG2E;

    // Scan range and wide detection: live window is contiguous around idx;
    // if a boundary element is live the window may extend beyond the scan.
    const int j0 = max(idx - WSCAN, 0);
    const int j1 = min(idx + WSCAN, D_DIM);
    bool wide = false;
    if (j0 > 0     && fabsf(fmaf(a, xs[j0],     bb) - q) < rthr) wide = true;
    if (j1 < D_DIM && fabsf(fmaf(a, xs[j1 - 1], bb) - q) < rthr) wide = true;

    if (!wide) {
        // Predicate-free scan: out-of-window terms underflow (p <= 2^-43);
        // including them only improves accuracy vs the reference.
        float S0 = 0.f, S1 = 0.f;
#pragma unroll 1
        for (int j = j0; j < j1; j++) {
            float xv   = xs[j];
            float draw = fabsf(fmaf(a, xv, bb) - q);
            float p    = ex2_fast(fmaf(frcp_approx(draw + EPSILON), LOG2E, c));
            S0 += p;
            S1 = fmaf(p, xv, S1);
        }
        satt[qloc][h] = 0.5f * fmaf(avh, S1 / S0, bvh);
    }

    // Warp-ballot cooperative pass for wide items: whole warp handles each
    // wide lane's item over the full row (lane-strided + shuffle reduce).
    unsigned wm = __ballot_sync(0xffffffffu, wide);
    while (wm) {
        const int src = __ffs(wm) - 1;
        wm &= wm - 1;
        const float qw = __shfl_sync(0xffffffffu, q,    src);
        const float aw = __shfl_sync(0xffffffffu, a,    src);
        const float bw = __shfl_sync(0xffffffffu, bb,   src);
        const float cw = __shfl_sync(0xffffffffu, c,    src);
        float S0 = 0.f, S1 = 0.f;
#pragma unroll 4
        for (int j = lane; j < D_DIM; j += 32) {
            float xv   = xs[j];
            float draw = fabsf(fmaf(aw, xv, bw) - qw);
            float p    = ex2_fast(fmaf(frcp_approx(draw + EPSILON), LOG2E, cw));
            S0 += p;
            S1 = fmaf(p, xv, S1);
        }
#pragma unroll
        for (int o = 16; o; o >>= 1) {
            S0 += __shfl_xor_sync(0xffffffffu, S0, o);
            S1 += __shfl_xor_sync(0xffffffffu, S1, o);
        }
        if (lane == src)
            satt[qloc][h] = 0.5f * fmaf(avh, S1 / S0, bvh);
    }
    __syncthreads();

    // Epilogue: combine heads + residual, one thread per query.
    if (tid < QPB) {
        int qq = i0 + tid;
        float r = __ldg(x + b * D_DIM + qq);
        out[b * D_DIM + qq] = r + satt[tid][0] + satt[tid][1]
                                + satt[tid][2] + satt[tid][3];
    }
}

extern "C" void kernel_launch(void* const* d_in, const int* in_sizes, int n_in,
                              void* d_out, int out_size)
{
    const float* x  = (const float*)d_in[0];
    const float* aq = (const float*)d_in[1];
    const float* bq = (const float*)d_in[2];
    const float* ak = (const float*)d_in[3];
    const float* bk = (const float*)d_in[4];
    const float* av = (const float*)d_in[5];
    const float* bv = (const float*)d_in[6];
    float* out = (float*)d_out;

    const int B = in_sizes[0] / D_DIM;              // 16
    sort_kernel<<<B, D_DIM>>>(x);
    attn_kernel<<<B * (D_DIM / QPB), TB>>>(x, aq, bq, ak, bk, av, bv, out);
}